// round 1
// baseline (speedup 1.0000x reference)
#include <cuda_runtime.h>
#include <cuda_bf16.h>
#include <stdint.h>

// Renderer_79147657330969 — NeRF-style volume rendering + NLL loss.
// One warp per ray, 4 samples per lane (S = 128).
// Inputs (metadata order): raw_rgb [N,128,3] f32, raw_sigma [N,128] f32,
//                          dists [N,128] f32 (UNUSED by reference), targets [N,3] f32
// Output: [ rgb_map (N*3 f32) | losses (N f32) ]

#define N_SAMPLES 128
#define FULL 0xffffffffu

__global__ __launch_bounds__(256) void renderer_kernel(
    const float* __restrict__ raw_rgb,
    const float* __restrict__ raw_sigma,
    const float* __restrict__ targets,
    float* __restrict__ out,
    int n_rays)
{
    const int warp_global = (blockIdx.x * blockDim.x + threadIdx.x) >> 5;
    const int lane = threadIdx.x & 31;
    if (warp_global >= n_rays) return;
    const int ray = warp_global;

    // ---- 1. sigma -> log_passed (lp), log_not_passed (lnp) ----
    // lp  = -softplus(x)  = -(log1p(exp(-|x|)) + max(x,0))
    // lnp = -softplus(-x) = x + lp
    float4 sg = __ldg(reinterpret_cast<const float4*>(raw_sigma) + (size_t)ray * (N_SAMPLES / 4) + lane);
    float sv[4] = { sg.x, sg.y, sg.z, sg.w };
    float lp[4], lnp[4];
#pragma unroll
    for (int i = 0; i < 4; i++) {
        float x = sv[i];
        float t = log1pf(__expf(-fabsf(x)));
        float l = -(t + fmaxf(x, 0.0f));
        lp[i]  = l;
        lnp[i] = x + l;
    }

    // ---- 2. exclusive prefix sum of lp across the 128 samples ----
    float c0 = lp[0];
    float c1 = c0 + lp[1];
    float c2 = c1 + lp[2];
    float c3 = c2 + lp[3];       // lane-local inclusive sums
    float s = c3;
#pragma unroll
    for (int off = 1; off < 32; off <<= 1) {
        float v = __shfl_up_sync(FULL, s, off);
        if (lane >= off) s += v;
    }
    const float excl  = s - c3;                          // sum of lp over all earlier lanes
    const float total = __shfl_sync(FULL, s, 31);        // sum of all 128 lp
    float logw[4];
    logw[0] = lnp[0] + excl;
    logw[1] = lnp[1] + excl + c0;
    logw[2] = lnp[2] + excl + c1;
    logw[3] = lnp[3] + excl + c2;
    // background log-weight = exclusive prefix at sample 127 = total - lp[127]
    const float lw_bg = total - __shfl_sync(FULL, lp[3], 31);

    // ---- 3. rgb: sigmoid + squared error vs target ----
    const float tx = __ldg(targets + (size_t)ray * 3 + 0);
    const float ty = __ldg(targets + (size_t)ray * 3 + 1);
    const float tz = __ldg(targets + (size_t)ray * 3 + 2);

    const float4* rp = reinterpret_cast<const float4*>(raw_rgb) + (size_t)ray * (N_SAMPLES * 3 / 4) + lane * 3;
    float4 r0 = __ldg(rp + 0);
    float4 r1 = __ldg(rp + 1);
    float4 r2 = __ldg(rp + 2);
    float rr[12] = { r0.x, r0.y, r0.z, r0.w,
                     r1.x, r1.y, r1.z, r1.w,
                     r2.x, r2.y, r2.z, r2.w };

    float lq[4];                 // log_p for this lane's 4 samples
    float ax = 0.0f, ay = 0.0f, az = 0.0f;   // rgb_map accumulators
#pragma unroll
    for (int i = 0; i < 4; i++) {
        float cr = __fdividef(1.0f, 1.0f + __expf(-rr[3 * i + 0]));
        float cg = __fdividef(1.0f, 1.0f + __expf(-rr[3 * i + 1]));
        float cb = __fdividef(1.0f, 1.0f + __expf(-rr[3 * i + 2]));
        float dx = cr - tx, dy = cg - ty, dz = cb - tz;
        float err = dx * dx + dy * dy + dz * dz;
        lq[i] = -0.5f * err + logw[i];
        float w = __expf(logw[i]);    // logw <= 0 -> no overflow
        ax = fmaf(w, cr, ax);
        ay = fmaf(w, cg, ay);
        az = fmaf(w, cb, az);
    }
    // background term (rgb = 0): log_p_bg = -0.5*|t|^2 + lw_bg ; contributes 0 to rgb_map
    const float lbg = -0.5f * (tx * tx + ty * ty + tz * tz) + lw_bg;

    // ---- 4. 129-way softmax + loss ----
    float m = fmaxf(fmaxf(fmaxf(lq[0], lq[1]), fmaxf(lq[2], lq[3])), lbg);
#pragma unroll
    for (int off = 16; off > 0; off >>= 1)
        m = fmaxf(m, __shfl_xor_sync(FULL, m, off));

    float se = 0.0f, sel = 0.0f;
#pragma unroll
    for (int i = 0; i < 4; i++) {
        float e = __expf(lq[i] - m);      // underflow -> 0 matches q==0 masking
        se  += e;
        sel = fmaf(e, lq[i], sel);
    }
    if (lane == 0) {                       // background counted exactly once
        float e = __expf(lbg - m);
        se  += e;
        sel = fmaf(e, lbg, sel);
    }

    // ---- 5. warp reductions + write ----
#pragma unroll
    for (int off = 16; off > 0; off >>= 1) {
        se  += __shfl_xor_sync(FULL, se,  off);
        sel += __shfl_xor_sync(FULL, sel, off);
        ax  += __shfl_xor_sync(FULL, ax,  off);
        ay  += __shfl_xor_sync(FULL, ay,  off);
        az  += __shfl_xor_sync(FULL, az,  off);
    }
    if (lane == 0) {
        out[(size_t)ray * 3 + 0] = ax;
        out[(size_t)ray * 3 + 1] = ay;
        out[(size_t)ray * 3 + 2] = az;
        out[(size_t)n_rays * 3 + ray] = -sel / se;   // losses block after rgb_map
    }
}

extern "C" void kernel_launch(void* const* d_in, const int* in_sizes, int n_in,
                              void* d_out, int out_size) {
    const float* raw_rgb   = (const float*)d_in[0];
    const float* raw_sigma = (const float*)d_in[1];
    // d_in[2] = dists — unused by the reference computation; deliberately not read.
    const float* targets   = (const float*)d_in[3];
    float* out = (float*)d_out;

    const int n_rays = in_sizes[1] / N_SAMPLES;      // raw_sigma element count / S
    const int threads = 256;                          // 8 warps = 8 rays per block
    const int blocks = (n_rays * 32 + threads - 1) / threads;
    renderer_kernel<<<blocks, threads>>>(raw_rgb, raw_sigma, targets, out, n_rays);
}

// round 2
// speedup vs baseline: 1.2862x; 1.2862x over previous
#include <cuda_runtime.h>
#include <cuda_bf16.h>
#include <stdint.h>

// Renderer_79147657330969 — NeRF volume rendering + NLL loss, linear-domain version.
// One warp per ray, 4 samples per lane (S = 128).
// Inputs: raw_rgb [N,128,3] f32, raw_sigma [N,128] f32, dists (unused), targets [N,3] f32
// Output: [ rgb_map (N*3 f32) | losses (N f32) ]

#define N_SAMPLES 128
#define FULL 0xffffffffu

__device__ __forceinline__ float fast_sigmoid(float x) {
    // sigmoid(x) = 0.5*tanh(x/2) + 0.5 via MUFU.TANH (sm_75+)
    float h = 0.5f * x, t;
    asm("tanh.approx.f32 %0, %1;" : "=f"(t) : "f"(h));
    return fmaf(t, 0.5f, 0.5f);
}

__global__ __launch_bounds__(256) void renderer_kernel(
    const float* __restrict__ raw_rgb,
    const float* __restrict__ raw_sigma,
    const float* __restrict__ targets,
    float* __restrict__ out,
    int n_rays)
{
    const int ray  = (blockIdx.x * blockDim.x + threadIdx.x) >> 5;
    const int lane = threadIdx.x & 31;
    if (ray >= n_rays) return;

    // ---- 1. transmittance probabilities (linear domain) ----
    // p_pass = sigmoid(-x) = 1/(1+e^x) ; np = sigmoid(x) = 1 - p_pass
    float4 sg = __ldg(reinterpret_cast<const float4*>(raw_sigma) + (size_t)ray * (N_SAMPLES / 4) + lane);
    float xv[4] = { sg.x, sg.y, sg.z, sg.w };
    float pp[4], np[4];
#pragma unroll
    for (int i = 0; i < 4; i++) {
        float p = __fdividef(1.0f, 1.0f + __expf(xv[i]));  // accurate when small (no cancellation)
        pp[i] = p;
        np[i] = 1.0f - p;
    }

    // ---- 2. exclusive prefix PRODUCT of p_pass over 128 samples ----
    float m0 = pp[0];
    float m1 = m0 * pp[1];
    float m2 = m1 * pp[2];
    float m3 = m2 * pp[3];          // lane-local inclusive products
    float s = m3;
#pragma unroll
    for (int off = 1; off < 32; off <<= 1) {
        float v = __shfl_up_sync(FULL, s, off);
        if (lane >= off) s *= v;
    }
    float excl = __shfl_up_sync(FULL, s, 1);   // product over all earlier lanes
    if (lane == 0) excl = 1.0f;
    // background weight = prod(p_pass[0..126]) = excl(lane31) * m2(lane31)
    const float w_bg = __shfl_sync(FULL, excl * m2, 31);

    float w[4];
    w[0] = np[0] * excl;
    w[1] = np[1] * (excl * m0);
    w[2] = np[2] * (excl * m1);
    w[3] = np[3] * (excl * m2);

    // ---- 3. rgb sigmoid + squared error + unnormalized softmax numerators ----
    const float tx = __ldg(targets + (size_t)ray * 3 + 0);
    const float ty = __ldg(targets + (size_t)ray * 3 + 1);
    const float tz = __ldg(targets + (size_t)ray * 3 + 2);

    const float4* rp = reinterpret_cast<const float4*>(raw_rgb) + (size_t)ray * (N_SAMPLES * 3 / 4) + lane * 3;
    float4 r0 = __ldg(rp + 0);
    float4 r1 = __ldg(rp + 1);
    float4 r2 = __ldg(rp + 2);
    float rr[12] = { r0.x, r0.y, r0.z, r0.w,
                     r1.x, r1.y, r1.z, r1.w,
                     r2.x, r2.y, r2.z, r2.w };

    float ax = 0.0f, ay = 0.0f, az = 0.0f;   // rgb_map accumulators
    float se = 0.0f, sel = 0.0f;             // sum p, sum p*log(p)
#pragma unroll
    for (int i = 0; i < 4; i++) {
        float cr = fast_sigmoid(rr[3 * i + 0]);
        float cg = fast_sigmoid(rr[3 * i + 1]);
        float cb = fast_sigmoid(rr[3 * i + 2]);
        float dx = cr - tx, dy = cg - ty, dz = cb - tz;
        float err = fmaf(dx, dx, fmaf(dy, dy, dz * dz));
        float wi = w[i];
        ax = fmaf(wi, cr, ax);
        ay = fmaf(wi, cg, ay);
        az = fmaf(wi, cb, az);
        // p = weight * exp(-err/2): unnormalized posterior; Sum p in [e^-1.5, 1] -> no max shift needed
        float p = wi * __expf(-0.5f * err);
        se += p;
        if (p > 0.0f) sel = fmaf(p, __logf(p), sel);   // p==0 <=> reference q==0 mask
    }
    if (lane == 0) {   // background sample: rgb = 0, contributes 0 to rgb_map
        float pbg = w_bg * __expf(-0.5f * fmaf(tx, tx, fmaf(ty, ty, tz * tz)));
        se += pbg;
        if (pbg > 0.0f) sel = fmaf(pbg, __logf(pbg), sel);
    }

    // ---- 4. warp reductions + write ----
#pragma unroll
    for (int off = 16; off > 0; off >>= 1) {
        se  += __shfl_xor_sync(FULL, se,  off);
        sel += __shfl_xor_sync(FULL, sel, off);
        ax  += __shfl_xor_sync(FULL, ax,  off);
        ay  += __shfl_xor_sync(FULL, ay,  off);
        az  += __shfl_xor_sync(FULL, az,  off);
    }
    if (lane == 0) {
        out[(size_t)ray * 3 + 0] = ax;
        out[(size_t)ray * 3 + 1] = ay;
        out[(size_t)ray * 3 + 2] = az;
        // loss = -sum(q * log_p) = -(sum p*log p)/(sum p)
        out[(size_t)n_rays * 3 + ray] = -__fdividef(sel, se);
    }
}

extern "C" void kernel_launch(void* const* d_in, const int* in_sizes, int n_in,
                              void* d_out, int out_size) {
    const float* raw_rgb   = (const float*)d_in[0];
    const float* raw_sigma = (const float*)d_in[1];
    // d_in[2] = dists — dead in the reference; never read (saves 33.6 MB of traffic).
    const float* targets   = (const float*)d_in[3];
    float* out = (float*)d_out;

    const int n_rays = in_sizes[1] / N_SAMPLES;
    const int threads = 256;                       // 8 warps = 8 rays / block
    const int blocks = (n_rays * 32 + threads - 1) / threads;
    renderer_kernel<<<blocks, threads>>>(raw_rgb, raw_sigma, targets, out, n_rays);
}